// round 16
// baseline (speedup 1.0000x reference)
#include <cuda_runtime.h>
#include <cuda_bf16.h>
#include <cstdint>

// ---------------------------------------------------------------------------
// Scratch: packed per-token segment ranges (T = 132096 here; headroom).
#define MAX_T 140000
__device__ int2 g_bounds[MAX_T];   // .x = start, .y = end
__device__ int  g_tile_ctr;        // work-stealing cursor

__global__ void init_ctr_kernel(int start) { g_tile_ctr = start; }

// Segments of one token are contiguous in seg_token_idx (built by
// repeat(token_rank, segs_per_token)); token ids are NOT sorted.
__global__ void seg_bounds_kernel(const int* __restrict__ idx, int S) {
    int i = blockIdx.x * blockDim.x + threadIdx.x;
    if (i >= S) return;
    int t = idx[i];
    if (i == 0 || idx[i - 1] != t) g_bounds[t].x = i;
    if (i == S - 1 || idx[i + 1] != t) g_bounds[t].y = i + 1;
}

// ---------------------------------------------------------------------------
__device__ __forceinline__ uint32_t smem_to_u32(const void* p) {
    uint32_t a;
    asm("{ .reg .u64 t; cvta.to.shared.u64 t, %1; cvt.u32.u64 %0, t; }"
        : "=r"(a) : "l"(p));
    return a;
}
__device__ __forceinline__ void ldsm_x4(uint32_t* r, uint32_t addr) {
    asm volatile("ldmatrix.sync.aligned.m8n8.x4.shared.b16 {%0,%1,%2,%3}, [%4];"
                 : "=r"(r[0]), "=r"(r[1]), "=r"(r[2]), "=r"(r[3]) : "r"(addr));
}
__device__ __forceinline__ void ldsm_x2(uint32_t& r0, uint32_t& r1, uint32_t addr) {
    asm volatile("ldmatrix.sync.aligned.m8n8.x2.shared.b16 {%0,%1}, [%2];"
                 : "=r"(r0), "=r"(r1) : "r"(addr));
}
__device__ __forceinline__ void hmma16816(float& c0, float& c1, float& c2, float& c3,
                                          uint32_t a0, uint32_t a1, uint32_t a2, uint32_t a3,
                                          uint32_t b0, uint32_t b1) {
    asm volatile(
        "mma.sync.aligned.m16n8k16.row.col.f32.bf16.bf16.f32 "
        "{%0,%1,%2,%3}, {%4,%5,%6,%7}, {%8,%9}, {%0,%1,%2,%3};"
        : "+f"(c0), "+f"(c1), "+f"(c2), "+f"(c3)
        : "r"(a0), "r"(a1), "r"(a2), "r"(a3), "r"(b0), "r"(b1));
}

// ---------------------------------------------------------------------------
// Split-bf16 GEMM, deduplicated fragments:
//   tok = th + tl, W = wh + wl;  out = th*wh + th*wl + tl*wh  (drop tl*wl).
// Token tile k-layout [0:32)=th, [32:64)=tl; W tile [0:32)=wh, [32:64)=wl.
// Column pairing -> per-thread 4 consecutive output cols -> STG.128.
// 1024 threads / 32 warps, one 16-col H group per warp (breg = 16 regs);
// un-staggered m-walk (dense 32KB store blocks — R13 lesson).
//
// This round: work-stealing tile cursor (kills the 7-vs-6 static tail),
// int2-packed bounds (1 LDG.64 instead of 2 LDG.32 per token), and plain
// STG (A/B vs __stcs).
static constexpr int TILE_TOK = 128;
static constexpr int ROWB     = 144;                 // bytes per k-row
static constexpr int SW_OFF   = 0;                   // W-split: 512 rows
static constexpr int SB_OFF   = 512 * ROWB;          // bias: 73728
static constexpr int SSTEAL   = SB_OFF + 2048;       // stolen-tile slot: 75776
static constexpr int ST0      = SSTEAL + 16;         // 75792 (16B aligned)
static constexpr int TBYTES   = TILE_TOK * ROWB;     // 18432
static constexpr int ST1      = ST0 + TBYTES;        // 94224
static constexpr int SMEM_TOTAL = ST1 + TBYTES;      // 112656

#define NTHREADS 1024   // 32 warps

template <bool EXACT>
__global__ __launch_bounds__(NTHREADS, 1) void fused_hmma_kernel(
    const float* __restrict__ features,   // [S, 32]
    const float* __restrict__ W,          // [32, 512]
    const float* __restrict__ b,          // [512]
    float* __restrict__ out,              // [T, 512]
    int T, int ntiles)
{
    extern __shared__ char smem[];
    const uint32_t smem_base = smem_to_u32(smem);
    const int tid  = threadIdx.x;
    const int wid  = tid >> 5;            // 0..31
    const int lane = tid & 31;

    // --- Stage W^T split (column-pair permuted) + bias (once per CTA) ---
    for (int idx = tid; idx < 32 * 512; idx += NTHREADS) {
        const int f = idx >> 9, h = idx & 511;       // coalesced LDG over h
        const float wv = W[idx];
        const __nv_bfloat16 hb = __float2bfloat16(wv);
        const __nv_bfloat16 lb = __float2bfloat16(wv - __bfloat162float(hb));
        const int g = h >> 4, p = h & 15;
        const int row = g * 16 + ((p >> 1) & 1) * 8 + 2 * (p >> 2) + (p & 1);
        char* r = smem + SW_OFF + row * ROWB;
        *(__nv_bfloat16*)(r + 2 * f)        = hb;    // wh  (k = f)
        *(__nv_bfloat16*)(r + 2 * (32 + f)) = lb;    // wl  (k = 32+f)
    }
    if (tid < 512) *(float*)(smem + SB_OFF + 4 * tid) = b[tid];
    __syncthreads();

    // --- Hoist W fragments: 2 tiles (e/o) x 4 k-steps x 2 regs = 16 regs ---
    const int wsl = wid * 16;
    uint32_t breg[2][4][2];
    {
        const uint32_t wb = smem_base + SW_OFF;
        #pragma unroll
        for (int eo = 0; eo < 2; eo++)
            #pragma unroll
            for (int ks = 0; ks < 4; ks++) {
                uint32_t addr = wb + (wsl + eo * 8 + (lane & 7)) * ROWB
                              + (ks * 16 + ((lane >> 3) & 1) * 8) * 2;
                ldsm_x2(breg[eo][ks][0], breg[eo][ks][1], addr);
            }
    }
    const int q = lane & 3;
    const float4 bias4 = *reinterpret_cast<const float4*>(
        smem + SB_OFF + (wsl + 4 * q) * 4);

    // --- Gather / convert (thread: f = lane, token row base = wid) ---
    const int f = lane, trow = wid;
    float ts[4];
    auto gather = [&](int tile_) {
        const int tok0 = tile_ * TILE_TOK;
        #pragma unroll
        for (int j = 0; j < 4; j++) {
            const int tok = tok0 + trow + 32 * j;
            int s0, n;
            if (EXACT || tok < T) {
                const int2 se = g_bounds[tok];       // one LDG.64 (broadcast)
                s0 = se.x;
                n  = se.y - se.x;
            } else { s0 = 0; n = 0; }
            const float* p = features + (uint32_t)(s0 * 32 + f);
            float a0 = (n > 0) ? __ldcs(p)      : 0.0f;
            float a1 = (n > 1) ? __ldcs(p + 32) : 0.0f;
            float a2 = (n > 2) ? __ldcs(p + 64) : 0.0f;
            float ex = 0.0f;
            for (int si = 3; si < n; si++) ex += __ldcs(p + 32 * si);
            ts[j] = 1e-10f + ((a0 + a1) + (a2 + ex));
        }
    };
    auto convert_sts = [&](char* B) {
        #pragma unroll
        for (int j = 0; j < 4; j++) {
            const int r = trow + 32 * j;
            const __nv_bfloat16 hb = __float2bfloat16(ts[j]);
            const __nv_bfloat16 lb =
                __float2bfloat16(ts[j] - __bfloat162float(hb));
            char* row = B + r * ROWB;
            *(__nv_bfloat16*)(row + 2 * f)        = hb;  // th (k = f)
            *(__nv_bfloat16*)(row + 2 * (32 + f)) = lb;  // tl (k = 32+f)
        }
    };

    // MMA + store for tile tcur out of buffer buf.
    auto mma_store = [&](int tcur, int buf) {
        const uint32_t cur = smem_base + (buf ? ST1 : ST0);
        const int tok0 = tcur * TILE_TOK;
        const uint32_t arow0 = cur + (lane & 15) * ROWB + ((lane >> 4) * 8) * 2;
        float* obase = out + (uint32_t)(tok0 + (lane >> 2)) * 512 + wsl + 4 * q;
        int rrow = tok0 + (lane >> 2);

        #pragma unroll 1
        for (int m = 0; m < 8; m++) {
            const uint32_t arow = arow0 + (uint32_t)m * (16 * ROWB);

            uint32_t a0[4], a1[4], a2[4], a3[4];
            ldsm_x4(a0, arow);
            ldsm_x4(a1, arow + 32);
            ldsm_x4(a2, arow + 64);
            ldsm_x4(a3, arow + 96);

            float e0 = bias4.x, e1 = bias4.y, e2 = e0, e3 = e1;
            float o0 = bias4.z, o1 = bias4.w, o2 = o0, o3 = o1;

            // th * wh, th * wl (both n-tiles)
            hmma16816(e0, e1, e2, e3, a0[0], a0[1], a0[2], a0[3],
                      breg[0][0][0], breg[0][0][1]);
            hmma16816(o0, o1, o2, o3, a0[0], a0[1], a0[2], a0[3],
                      breg[1][0][0], breg[1][0][1]);
            hmma16816(e0, e1, e2, e3, a1[0], a1[1], a1[2], a1[3],
                      breg[0][1][0], breg[0][1][1]);
            hmma16816(o0, o1, o2, o3, a1[0], a1[1], a1[2], a1[3],
                      breg[1][1][0], breg[1][1][1]);
            hmma16816(e0, e1, e2, e3, a0[0], a0[1], a0[2], a0[3],
                      breg[0][2][0], breg[0][2][1]);
            hmma16816(o0, o1, o2, o3, a0[0], a0[1], a0[2], a0[3],
                      breg[1][2][0], breg[1][2][1]);
            hmma16816(e0, e1, e2, e3, a1[0], a1[1], a1[2], a1[3],
                      breg[0][3][0], breg[0][3][1]);
            hmma16816(o0, o1, o2, o3, a1[0], a1[1], a1[2], a1[3],
                      breg[1][3][0], breg[1][3][1]);
            // tl * wh (both n-tiles)
            hmma16816(e0, e1, e2, e3, a2[0], a2[1], a2[2], a2[3],
                      breg[0][0][0], breg[0][0][1]);
            hmma16816(o0, o1, o2, o3, a2[0], a2[1], a2[2], a2[3],
                      breg[1][0][0], breg[1][0][1]);
            hmma16816(e0, e1, e2, e3, a3[0], a3[1], a3[2], a3[3],
                      breg[0][1][0], breg[0][1][1]);
            hmma16816(o0, o1, o2, o3, a3[0], a3[1], a3[2], a3[3],
                      breg[1][1][0], breg[1][1][1]);

            // Plain STG.128 (A/B vs __stcs); dense 32KB blocks per m-step.
            if (EXACT || rrow < T)
                *reinterpret_cast<float4*>(obase) =
                    make_float4(e0, e1, o0, o1);
            if (EXACT || rrow + 8 < T)
                *reinterpret_cast<float4*>(obase + 8 * 512) =
                    make_float4(e2, e3, o2, o3);
            obase += 16 * 512;
            if (!EXACT) rrow += 16;
        }
    };

    volatile int* s_steal = (volatile int*)(smem + SSTEAL);

    // --- Prologue: tile = blockIdx.x (grid clamped to <= ntiles) ---
    int tcur = blockIdx.x;
    gather(tcur);
    convert_sts(smem + ST0);
    if (tid == 0) *s_steal = atomicAdd(&g_tile_ctr, 1);
    __syncthreads();
    int tnext = *s_steal;

    int buf = 0;
    while (true) {
        const bool has_next = tnext < ntiles;

        // Prefetch next tile's gather + steal the tile after it.
        if (has_next) gather(tnext);
        if (tid == 0) *s_steal = atomicAdd(&g_tile_ctr, 1);

        mma_store(tcur, buf);

        if (has_next) convert_sts(smem + (buf ? ST0 : ST1));
        __syncthreads();
        if (!has_next) break;
        tcur = tnext;
        tnext = *s_steal;
        buf ^= 1;
    }
}

// ---------------------------------------------------------------------------
extern "C" void kernel_launch(void* const* d_in, const int* in_sizes, int n_in,
                              void* d_out, int out_size) {
    const float* features = (const float*)d_in[0];   // [S, 32]
    const float* W        = (const float*)d_in[1];   // [32, 512]
    const float* b        = (const float*)d_in[2];   // [512]
    const int*   idx      = (const int*)d_in[3];     // [S]
    float*       out      = (float*)d_out;           // [T, 512]

    const int S = in_sizes[3];
    const int T = out_size / 512;
    const int ntiles = (T + TILE_TOK - 1) / TILE_TOK;

    static int nsm = 0;
    if (nsm == 0) {
        // First call is the (non-captured) correctness run; cached afterwards.
        cudaDeviceGetAttribute(&nsm, cudaDevAttrMultiProcessorCount, 0);
        if (nsm <= 0) nsm = 148;
        cudaFuncSetAttribute(fused_hmma_kernel<true>,
                             cudaFuncAttributeMaxDynamicSharedMemorySize,
                             SMEM_TOTAL);
        cudaFuncSetAttribute(fused_hmma_kernel<false>,
                             cudaFuncAttributeMaxDynamicSharedMemorySize,
                             SMEM_TOTAL);
    }

    int grid = nsm;
    if (grid > ntiles) grid = ntiles;

    seg_bounds_kernel<<<(S + 255) / 256, 256>>>(idx, S);
    init_ctr_kernel<<<1, 1>>>(grid);   // stolen tiles start after static ones

    if (T % TILE_TOK == 0)
        fused_hmma_kernel<true><<<grid, NTHREADS, SMEM_TOTAL>>>(
            features, W, b, out, T, ntiles);
    else
        fused_hmma_kernel<false><<<grid, NTHREADS, SMEM_TOTAL>>>(
            features, W, b, out, T, ntiles);
}

// round 17
// speedup vs baseline: 1.1186x; 1.1186x over previous
#include <cuda_runtime.h>
#include <cuda_bf16.h>
#include <cstdint>

// ---------------------------------------------------------------------------
// Scratch: packed per-token segment ranges (T = 132096 here; headroom).
#define MAX_T 140000
__device__ int2 g_bounds[MAX_T];   // .x = start, .y = end

// Segments of one token are contiguous in seg_token_idx (built by
// repeat(token_rank, segs_per_token)); token ids are NOT sorted.
__global__ void seg_bounds_kernel(const int* __restrict__ idx, int S) {
    int i = blockIdx.x * blockDim.x + threadIdx.x;
    if (i >= S) return;
    int t = idx[i];
    if (i == 0 || idx[i - 1] != t) g_bounds[t].x = i;
    if (i == S - 1 || idx[i + 1] != t) g_bounds[t].y = i + 1;
}

// ---------------------------------------------------------------------------
__device__ __forceinline__ uint32_t smem_to_u32(const void* p) {
    uint32_t a;
    asm("{ .reg .u64 t; cvta.to.shared.u64 t, %1; cvt.u32.u64 %0, t; }"
        : "=r"(a) : "l"(p));
    return a;
}
__device__ __forceinline__ void ldsm_x4(uint32_t* r, uint32_t addr) {
    asm volatile("ldmatrix.sync.aligned.m8n8.x4.shared.b16 {%0,%1,%2,%3}, [%4];"
                 : "=r"(r[0]), "=r"(r[1]), "=r"(r[2]), "=r"(r[3]) : "r"(addr));
}
__device__ __forceinline__ void ldsm_x2(uint32_t& r0, uint32_t& r1, uint32_t addr) {
    asm volatile("ldmatrix.sync.aligned.m8n8.x2.shared.b16 {%0,%1}, [%2];"
                 : "=r"(r0), "=r"(r1) : "r"(addr));
}
__device__ __forceinline__ void hmma16816(float& c0, float& c1, float& c2, float& c3,
                                          uint32_t a0, uint32_t a1, uint32_t a2, uint32_t a3,
                                          uint32_t b0, uint32_t b1) {
    asm volatile(
        "mma.sync.aligned.m16n8k16.row.col.f32.bf16.bf16.f32 "
        "{%0,%1,%2,%3}, {%4,%5,%6,%7}, {%8,%9}, {%0,%1,%2,%3};"
        : "+f"(c0), "+f"(c1), "+f"(c2), "+f"(c3)
        : "r"(a0), "r"(a1), "r"(a2), "r"(a3), "r"(b0), "r"(b1));
}

// ---------------------------------------------------------------------------
// Split-bf16 GEMM, deduplicated fragments:
//   tok = th + tl, W = wh + wl;  out = th*wh + th*wl + tl*wh  (drop tl*wl).
// Token tile k-layout [0:32)=th, [32:64)=tl; W tile [0:32)=wh, [32:64)=wl.
//
// Column pairing: within each 16-col H group, n-tile "e" covers physical cols
// {4q, 4q+1} and "o" covers {4q+2, 4q+3} (q = lane&3) -> STG.128 per row.
// W staging permutes: phys col p -> row g*16 + ((p>>1)&1)*8 + 2*(p>>2) + (p&1).
//
// 1024 threads / 32 warps, one 16-col H group per warp -> breg = 16 regs,
// <=64 regs/thread (hard RF ceiling), occupancy 32 warps/SM.
//
// LOCKED-IN LESSONS:
//  - __stcs streaming stores are load-bearing (R16 removing them: +7us).
//  - Un-staggered m-walk is load-bearing: 32 warps jointly write one dense
//    32KB block per m-step (R13 staggering: +16us).
//  - Static tile schedule; work-stealing overhead not worth it (R16).
//
// smem rows 72 bf16 = 144 B (36 words): 8-row ldmatrix sets conflict-free.
static constexpr int TILE_TOK = 128;
static constexpr int ROWB     = 144;                 // bytes per k-row
static constexpr int SW_OFF   = 0;                   // W-split: 512 rows
static constexpr int SB_OFF   = 512 * ROWB;          // bias: 73728
static constexpr int ST0      = SB_OFF + 2048;       // 75776
static constexpr int TBYTES   = TILE_TOK * ROWB;     // 18432
static constexpr int ST1      = ST0 + TBYTES;        // 94208
static constexpr int SMEM_TOTAL = ST1 + TBYTES;      // 112640

#define NTHREADS 1024   // 32 warps

template <bool EXACT>
__global__ __launch_bounds__(NTHREADS, 1) void fused_hmma_kernel(
    const float* __restrict__ features,   // [S, 32]
    const float* __restrict__ W,          // [32, 512]
    const float* __restrict__ b,          // [512]
    float* __restrict__ out,              // [T, 512]
    int T, int ntiles)
{
    extern __shared__ char smem[];
    const uint32_t smem_base = smem_to_u32(smem);
    const int tid  = threadIdx.x;
    const int wid  = tid >> 5;            // 0..31
    const int lane = tid & 31;

    // --- Stage W^T split (column-pair permuted) + bias (once per CTA) ---
    for (int idx = tid; idx < 32 * 512; idx += NTHREADS) {
        const int f = idx >> 9, h = idx & 511;       // coalesced LDG over h
        const float wv = W[idx];
        const __nv_bfloat16 hb = __float2bfloat16(wv);
        const __nv_bfloat16 lb = __float2bfloat16(wv - __bfloat162float(hb));
        const int g = h >> 4, p = h & 15;
        const int row = g * 16 + ((p >> 1) & 1) * 8 + 2 * (p >> 2) + (p & 1);
        char* r = smem + SW_OFF + row * ROWB;
        *(__nv_bfloat16*)(r + 2 * f)        = hb;    // wh  (k = f)
        *(__nv_bfloat16*)(r + 2 * (32 + f)) = lb;    // wl  (k = 32+f)
    }
    if (tid < 512) *(float*)(smem + SB_OFF + 4 * tid) = b[tid];
    __syncthreads();

    // --- Hoist W fragments: 2 tiles (e/o) x 4 k-steps x 2 regs = 16 regs ---
    const int wsl = wid * 16;             // global H base of this warp
    uint32_t breg[2][4][2];
    {
        const uint32_t wb = smem_base + SW_OFF;
        #pragma unroll
        for (int eo = 0; eo < 2; eo++)
            #pragma unroll
            for (int ks = 0; ks < 4; ks++) {
                uint32_t addr = wb + (wsl + eo * 8 + (lane & 7)) * ROWB
                              + (ks * 16 + ((lane >> 3) & 1) * 8) * 2;
                ldsm_x2(breg[eo][ks][0], breg[eo][ks][1], addr);
            }
    }
    const int q = lane & 3;
    // Bias: loop-invariant, loaded ONCE into registers.
    const float4 bias4 = *reinterpret_cast<const float4*>(
        smem + SB_OFF + (wsl + 4 * q) * 4);

    int tile = blockIdx.x;
    if (tile >= ntiles) return;   // grid is clamped; defensive (uniform per CTA)

    // --- Gather: thread (f = lane, token row base = wid) ---
    const int f = lane, trow = wid;
    float ts[4];
    auto gather = [&](int tile_) {
        const int tok0 = tile_ * TILE_TOK;
        #pragma unroll
        for (int j = 0; j < 4; j++) {
            const int tok = tok0 + trow + 32 * j;
            int s0, n;
            if (EXACT || tok < T) {
                const int2 se = g_bounds[tok];       // one LDG.64 (broadcast)
                s0 = se.x;
                n  = se.y - se.x;
            } else { s0 = 0; n = 0; }
            // 32-bit offset math (s0*32+f < 2^31): no IMAD.HI chains.
            const float* p = features + (uint32_t)(s0 * 32 + f);
            float a0 = (n > 0) ? __ldcs(p)      : 0.0f;
            float a1 = (n > 1) ? __ldcs(p + 32) : 0.0f;
            float a2 = (n > 2) ? __ldcs(p + 64) : 0.0f;
            float ex = 0.0f;
            for (int si = 3; si < n; si++) ex += __ldcs(p + 32 * si);
            ts[j] = 1e-10f + ((a0 + a1) + (a2 + ex));
        }
    };
    auto convert_sts = [&](char* B) {
        #pragma unroll
        for (int j = 0; j < 4; j++) {
            const int r = trow + 32 * j;
            const __nv_bfloat16 hb = __float2bfloat16(ts[j]);
            const __nv_bfloat16 lb =
                __float2bfloat16(ts[j] - __bfloat162float(hb));
            char* row = B + r * ROWB;
            *(__nv_bfloat16*)(row + 2 * f)        = hb;  // th (k = f)
            *(__nv_bfloat16*)(row + 2 * (32 + f)) = lb;  // tl (k = 32+f)
        }
    };

    // Prime the pipeline.
    gather(tile);
    convert_sts(smem + ST0);
    __syncthreads();

    int buf = 0;
    while (true) {
        const int next = tile + gridDim.x;
        const bool has_next = next < ntiles;

        // Prefetch next tile's gather LDGs (consumed after the MMA phase).
        if (has_next) gather(next);

        // --- MMA + store phase on current buffer ---
        const uint32_t cur = smem_base + (buf ? ST1 : ST0);
        const int tok0 = tile * TILE_TOK;
        const uint32_t arow0 = cur + (lane & 15) * ROWB + ((lane >> 4) * 8) * 2;
        // Output pointer for m=0; strength-reduced by 16 rows per m-step.
        float* obase = out + (uint32_t)(tok0 + (lane >> 2)) * 512 + wsl + 4 * q;
        int rrow = tok0 + (lane >> 2);

        #pragma unroll 1
        for (int m = 0; m < 8; m++) {
            const uint32_t arow = arow0 + (uint32_t)m * (16 * ROWB);

            // All 4 fragment loads issued up front: a2/a3 latency overlaps
            // the th-HMMA block below.
            uint32_t a0[4], a1[4], a2[4], a3[4];
            ldsm_x4(a0, arow);
            ldsm_x4(a1, arow + 32);
            ldsm_x4(a2, arow + 64);
            ldsm_x4(a3, arow + 96);

            float e0 = bias4.x, e1 = bias4.y, e2 = e0, e3 = e1;
            float o0 = bias4.z, o1 = bias4.w, o2 = o0, o3 = o1;

            // th * wh, th * wl (both n-tiles)
            hmma16816(e0, e1, e2, e3, a0[0], a0[1], a0[2], a0[3],
                      breg[0][0][0], breg[0][0][1]);
            hmma16816(o0, o1, o2, o3, a0[0], a0[1], a0[2], a0[3],
                      breg[1][0][0], breg[1][0][1]);
            hmma16816(e0, e1, e2, e3, a1[0], a1[1], a1[2], a1[3],
                      breg[0][1][0], breg[0][1][1]);
            hmma16816(o0, o1, o2, o3, a1[0], a1[1], a1[2], a1[3],
                      breg[1][1][0], breg[1][1][1]);
            hmma16816(e0, e1, e2, e3, a0[0], a0[1], a0[2], a0[3],
                      breg[0][2][0], breg[0][2][1]);
            hmma16816(o0, o1, o2, o3, a0[0], a0[1], a0[2], a0[3],
                      breg[1][2][0], breg[1][2][1]);
            hmma16816(e0, e1, e2, e3, a1[0], a1[1], a1[2], a1[3],
                      breg[0][3][0], breg[0][3][1]);
            hmma16816(o0, o1, o2, o3, a1[0], a1[1], a1[2], a1[3],
                      breg[1][3][0], breg[1][3][1]);
            // tl * wh (both n-tiles)
            hmma16816(e0, e1, e2, e3, a2[0], a2[1], a2[2], a2[3],
                      breg[0][0][0], breg[0][0][1]);
            hmma16816(o0, o1, o2, o3, a2[0], a2[1], a2[2], a2[3],
                      breg[1][0][0], breg[1][0][1]);
            hmma16816(e0, e1, e2, e3, a3[0], a3[1], a3[2], a3[3],
                      breg[0][1][0], breg[0][1][1]);
            hmma16816(o0, o1, o2, o3, a3[0], a3[1], a3[2], a3[3],
                      breg[1][1][0], breg[1][1][1]);

            // Streaming stores: 4 consecutive cols -> one STG.128 per row.
            // All 32 warps together cover a dense 32KB block per m-step.
            if (EXACT || rrow < T)
                __stcs(reinterpret_cast<float4*>(obase),
                       make_float4(e0, e1, o0, o1));
            if (EXACT || rrow + 8 < T)
                __stcs(reinterpret_cast<float4*>(obase + 8 * 512),
                       make_float4(e2, e3, o2, o3));
            obase += 16 * 512;
            if (!EXACT) rrow += 16;
        }

        // Write next tile's token buffer; one sync per tile.
        if (has_next) convert_sts(smem + (buf ? ST0 : ST1));
        __syncthreads();
        if (!has_next) break;
        tile = next;
        buf ^= 1;
    }
}

// ---------------------------------------------------------------------------
extern "C" void kernel_launch(void* const* d_in, const int* in_sizes, int n_in,
                              void* d_out, int out_size) {
    const float* features = (const float*)d_in[0];   // [S, 32]
    const float* W        = (const float*)d_in[1];   // [32, 512]
    const float* b        = (const float*)d_in[2];   // [512]
    const int*   idx      = (const int*)d_in[3];     // [S]
    float*       out      = (float*)d_out;           // [T, 512]

    const int S = in_sizes[3];
    const int T = out_size / 512;
    const int ntiles = (T + TILE_TOK - 1) / TILE_TOK;

    static int nsm = 0;
    if (nsm == 0) {
        // First call is the (non-captured) correctness run; cached afterwards.
        cudaDeviceGetAttribute(&nsm, cudaDevAttrMultiProcessorCount, 0);
        if (nsm <= 0) nsm = 148;
        cudaFuncSetAttribute(fused_hmma_kernel<true>,
                             cudaFuncAttributeMaxDynamicSharedMemorySize,
                             SMEM_TOTAL);
        cudaFuncSetAttribute(fused_hmma_kernel<false>,
                             cudaFuncAttributeMaxDynamicSharedMemorySize,
                             SMEM_TOTAL);
    }

    seg_bounds_kernel<<<(S + 255) / 256, 256>>>(idx, S);

    int grid = nsm;
    if (grid > ntiles) grid = ntiles;
    if (T % TILE_TOK == 0)
        fused_hmma_kernel<true><<<grid, NTHREADS, SMEM_TOTAL>>>(
            features, W, b, out, T, ntiles);
    else
        fused_hmma_kernel<false><<<grid, NTHREADS, SMEM_TOTAL>>>(
            features, W, b, out, T, ntiles);
}